// round 2
// baseline (speedup 1.0000x reference)
#include <cuda_runtime.h>
#include <math.h>

#define HD 128
#define TILE 32
#define THREADS 256

// Pre-transposed forward weights: slot0=W_in^T, slot1..4=Wl[i]^T, slot5=W_out^T
__device__ float g_wt[6 * HD * HD];
// sin(t*fw + fb) per layer
__device__ float g_cvec[4 * HD];

__global__ void prep_kernel(const float* __restrict__ t, const float* __restrict__ fw,
                            const float* __restrict__ fb, const float* __restrict__ W_in,
                            const float* __restrict__ Wl, const float* __restrict__ W_out) {
    int b = blockIdx.x;
    if (b < 6) {
        const float* src = (b == 0) ? W_in : (b <= 4 ? Wl + (b - 1) * HD * HD : W_out);
        float* dst = g_wt + b * HD * HD;
        for (int idx = threadIdx.x; idx < HD * HD; idx += blockDim.x) {
            int r = idx >> 7, c = idx & 127;
            dst[c * HD + r] = src[idx];
        }
    } else {
        float tv = t[0];
        for (int idx = threadIdx.x; idx < 4 * HD; idx += blockDim.x)
            g_cvec[idx] = sinf(tv * fw[idx] + fb[idx]);
    }
}

__device__ __forceinline__ float wsum(float v) {
#pragma unroll
    for (int o = 16; o > 0; o >>= 1) v += __shfl_xor_sync(0xffffffffu, v, o);
    return v;
}

__device__ __forceinline__ float softplus_f(float x) {
    return fmaxf(x, 0.f) + log1pf(expf(-fabsf(x)));
}

__device__ __forceinline__ void stage16k(float* __restrict__ dst, const float* __restrict__ src,
                                         int tid) {
    const float4* s = reinterpret_cast<const float4*>(src);
    float4* d = reinterpret_cast<float4*>(dst);
#pragma unroll
    for (int i = 0; i < (HD * HD / 4) / THREADS; i++) d[tid + i * THREADS] = s[tid + i * THREADS];
}

// C[r][o] = sum_i A[r][i] * M[i][o]; warp owns rows r0..r0+3, lane owns cols c0..c0+3
__device__ __forceinline__ void gemm32(const float* __restrict__ sA, const float* __restrict__ sM,
                                       float acc[4][4], int r0, int c0) {
#pragma unroll
    for (int rr = 0; rr < 4; rr++)
#pragma unroll
        for (int cc = 0; cc < 4; cc++) acc[rr][cc] = 0.f;
#pragma unroll 8
    for (int k = 0; k < HD; k++) {
        float4 m = *reinterpret_cast<const float4*>(&sM[k * HD + c0]);
#pragma unroll
        for (int rr = 0; rr < 4; rr++) {
            float a = sA[(r0 + rr) * HD + k];
            acc[rr][0] = fmaf(a, m.x, acc[rr][0]);
            acc[rr][1] = fmaf(a, m.y, acc[rr][1]);
            acc[rr][2] = fmaf(a, m.z, acc[rr][2]);
            acc[rr][3] = fmaf(a, m.w, acc[rr][3]);
        }
    }
}

__global__ __launch_bounds__(THREADS) void fused_kernel(
    const float* __restrict__ p, const float* __restrict__ w,
    const float* __restrict__ W_in, const float* __restrict__ b_in,
    const float* __restrict__ gamma, const float* __restrict__ beta,
    const float* __restrict__ Wl, const float* __restrict__ bl,
    const float* __restrict__ W_out, const float* __restrict__ b_out,
    float* __restrict__ dp, float* __restrict__ dw) {
    extern __shared__ float smem[];
    float* sM = smem;                    // HD*HD        (weights)
    float* sA = sM + HD * HD;            // TILE*HD      (GEMM A operand)
    float* sU = sA + TILE * HD;          // 4*TILE*HD    (layer-input checkpoints)
    float* sStats = sU + 4 * TILE * HD;  // 4*TILE*2     (mu, inv_sigma)

    const int tid = threadIdx.x;
    const int lane = tid & 31, warp = tid >> 5;
    const int r0 = warp * 4, c0 = lane * 4;
    const size_t rowBase = (size_t)blockIdx.x * TILE;

    float acc[4][4];

    // ---------------- forward ----------------
    {
        const float4* src = reinterpret_cast<const float4*>(p + rowBase * HD);
        float4* d = reinterpret_cast<float4*>(sA);
#pragma unroll
        for (int i = 0; i < (TILE * HD / 4) / THREADS; i++) d[tid + i * THREADS] = src[tid + i * THREADS];
    }
    stage16k(sM, g_wt, tid);
    __syncthreads();
    gemm32(sA, sM, acc, r0, c0);
    {
        float4 b = *reinterpret_cast<const float4*>(&b_in[c0]);
#pragma unroll
        for (int rr = 0; rr < 4; rr++) {
            acc[rr][0] += b.x; acc[rr][1] += b.y; acc[rr][2] += b.z; acc[rr][3] += b.w;
        }
    }

#pragma unroll 1
    for (int i = 0; i < 4; i++) {
        float4 cv = *reinterpret_cast<const float4*>(&g_cvec[i * HD + c0]);
        float4 gm = *reinterpret_cast<const float4*>(&gamma[i * HD + c0]);
        float4 bt = *reinterpret_cast<const float4*>(&beta[i * HD + c0]);
        float nv[4][4];
#pragma unroll
        for (int rr = 0; rr < 4; rr++) {
            // checkpoint u_i
            *reinterpret_cast<float4*>(&sU[(i * TILE + r0 + rr) * HD + c0]) =
                make_float4(acc[rr][0], acc[rr][1], acc[rr][2], acc[rr][3]);
            float s0 = softplus_f(acc[rr][0] + cv.x);
            float s1 = softplus_f(acc[rr][1] + cv.y);
            float s2 = softplus_f(acc[rr][2] + cv.z);
            float s3 = softplus_f(acc[rr][3] + cv.w);
            float mu = wsum(s0 + s1 + s2 + s3) * (1.f / HD);
            float d0 = s0 - mu, d1 = s1 - mu, d2 = s2 - mu, d3 = s3 - mu;
            float var = wsum(d0 * d0 + d1 * d1 + d2 * d2 + d3 * d3) * (1.f / HD);
            float inv = rsqrtf(var + 1e-5f);
            if (lane == 0) {
                sStats[(i * TILE + r0 + rr) * 2] = mu;
                sStats[(i * TILE + r0 + rr) * 2 + 1] = inv;
            }
            nv[rr][0] = d0 * inv * gm.x + bt.x;
            nv[rr][1] = d1 * inv * gm.y + bt.y;
            nv[rr][2] = d2 * inv * gm.z + bt.z;
            nv[rr][3] = d3 * inv * gm.w + bt.w;
        }
        __syncthreads();
#pragma unroll
        for (int rr = 0; rr < 4; rr++)
            *reinterpret_cast<float4*>(&sA[(r0 + rr) * HD + c0]) =
                make_float4(nv[rr][0], nv[rr][1], nv[rr][2], nv[rr][3]);
        stage16k(sM, g_wt + (1 + i) * HD * HD, tid);
        __syncthreads();
        gemm32(sA, sM, acc, r0, c0);
        float4 b = *reinterpret_cast<const float4*>(&bl[i * HD + c0]);
#pragma unroll
        for (int rr = 0; rr < 4; rr++) {
            acc[rr][0] += b.x; acc[rr][1] += b.y; acc[rr][2] += b.z; acc[rr][3] += b.w;
        }
    }

    // output projection -> dp
    __syncthreads();
#pragma unroll
    for (int rr = 0; rr < 4; rr++)
        *reinterpret_cast<float4*>(&sA[(r0 + rr) * HD + c0]) =
            make_float4(acc[rr][0], acc[rr][1], acc[rr][2], acc[rr][3]);
    stage16k(sM, g_wt + 5 * HD * HD, tid);
    __syncthreads();
    gemm32(sA, sM, acc, r0, c0);
    {
        float4 b = *reinterpret_cast<const float4*>(&b_out[c0]);
#pragma unroll
        for (int rr = 0; rr < 4; rr++) {
            float4 v = make_float4(acc[rr][0] + b.x, acc[rr][1] + b.y,
                                   acc[rr][2] + b.z, acc[rr][3] + b.w);
            *reinterpret_cast<float4*>(&dp[(rowBase + r0 + rr) * HD + c0]) = v;
        }
    }

    // ---------------- backward ----------------
    __syncthreads();
    {
        const float4* src = reinterpret_cast<const float4*>(w + rowBase * HD);
        float4* d = reinterpret_cast<float4*>(sA);
#pragma unroll
        for (int i = 0; i < (TILE * HD / 4) / THREADS; i++) d[tid + i * THREADS] = src[tid + i * THREADS];
    }
    stage16k(sM, W_out, tid);  // raw row-major == needed transpose-free layout
    __syncthreads();
    gemm32(sA, sM, acc, r0, c0);  // g = W_out^T w  (grad at h_L)

#pragma unroll 1
    for (int i = 3; i >= 0; i--) {
        __syncthreads();
#pragma unroll
        for (int rr = 0; rr < 4; rr++)
            *reinterpret_cast<float4*>(&sA[(r0 + rr) * HD + c0]) =
                make_float4(acc[rr][0], acc[rr][1], acc[rr][2], acc[rr][3]);
        stage16k(sM, Wl + i * HD * HD, tid);  // raw
        __syncthreads();
        gemm32(sA, sM, acc, r0, c0);  // gn = Wl_i^T g
        float4 cv = *reinterpret_cast<const float4*>(&g_cvec[i * HD + c0]);
        float4 gm = *reinterpret_cast<const float4*>(&gamma[i * HD + c0]);
#pragma unroll
        for (int rr = 0; rr < 4; rr++) {
            float4 u = *reinterpret_cast<const float4*>(&sU[(i * TILE + r0 + rr) * HD + c0]);
            float mu = sStats[(i * TILE + r0 + rr) * 2];
            float inv = sStats[(i * TILE + r0 + rr) * 2 + 1];
            float a0 = u.x + cv.x, a1 = u.y + cv.y, a2 = u.z + cv.z, a3 = u.w + cv.w;
            float sg0 = 1.f / (1.f + expf(-a0)), sg1 = 1.f / (1.f + expf(-a1));
            float sg2 = 1.f / (1.f + expf(-a2)), sg3 = 1.f / (1.f + expf(-a3));
            float xh0 = (softplus_f(a0) - mu) * inv, xh1 = (softplus_f(a1) - mu) * inv;
            float xh2 = (softplus_f(a2) - mu) * inv, xh3 = (softplus_f(a3) - mu) * inv;
            float gx0 = acc[rr][0] * gm.x, gx1 = acc[rr][1] * gm.y;
            float gx2 = acc[rr][2] * gm.z, gx3 = acc[rr][3] * gm.w;
            float m1 = wsum(gx0 + gx1 + gx2 + gx3) * (1.f / HD);
            float m2 = wsum(gx0 * xh0 + gx1 * xh1 + gx2 * xh2 + gx3 * xh3) * (1.f / HD);
            acc[rr][0] = inv * (gx0 - m1 - xh0 * m2) * sg0;
            acc[rr][1] = inv * (gx1 - m1 - xh1 * m2) * sg1;
            acc[rr][2] = inv * (gx2 - m1 - xh2 * m2) * sg2;
            acc[rr][3] = inv * (gx3 - m1 - xh3 * m2) * sg3;
        }
    }

    __syncthreads();
#pragma unroll
    for (int rr = 0; rr < 4; rr++)
        *reinterpret_cast<float4*>(&sA[(r0 + rr) * HD + c0]) =
            make_float4(acc[rr][0], acc[rr][1], acc[rr][2], acc[rr][3]);
    stage16k(sM, W_in, tid);  // raw
    __syncthreads();
    gemm32(sA, sM, acc, r0, c0);  // gp = W_in^T g
#pragma unroll
    for (int rr = 0; rr < 4; rr++)
        *reinterpret_cast<float4*>(&dw[(rowBase + r0 + rr) * HD + c0]) =
            make_float4(-acc[rr][0], -acc[rr][1], -acc[rr][2], -acc[rr][3]);
}

extern "C" void kernel_launch(void* const* d_in, const int* in_sizes, int n_in,
                              void* d_out, int out_size) {
    const float* t     = (const float*)d_in[0];
    const float* p     = (const float*)d_in[1];
    const float* w     = (const float*)d_in[2];
    const float* W_in  = (const float*)d_in[3];
    const float* b_in  = (const float*)d_in[4];
    const float* fw    = (const float*)d_in[5];
    const float* fb    = (const float*)d_in[6];
    const float* gamma = (const float*)d_in[7];
    const float* beta  = (const float*)d_in[8];
    const float* Wl    = (const float*)d_in[9];
    const float* bl    = (const float*)d_in[10];
    const float* W_out = (const float*)d_in[11];
    const float* b_out = (const float*)d_in[12];

    int nrows = in_sizes[1] / HD;  // B
    float* dp = (float*)d_out;
    float* dw = dp + (size_t)nrows * HD;

    size_t smem = (size_t)(HD * HD + TILE * HD + 4 * TILE * HD + 4 * TILE * 2) * sizeof(float);
    cudaFuncSetAttribute(fused_kernel, cudaFuncAttributeMaxDynamicSharedMemorySize, (int)smem);

    prep_kernel<<<7, 256>>>(t, fw, fb, W_in, Wl, W_out);
    fused_kernel<<<nrows / TILE, THREADS, smem>>>(p, w, W_in, b_in, gamma, beta, Wl, bl,
                                                  W_out, b_out, dp, dw);
}

// round 3
// speedup vs baseline: 1.9108x; 1.9108x over previous
#include <cuda_runtime.h>
#include <math.h>

#define HD 128
#define TILE 64
#define THREADS 256
#define NB 131072

typedef unsigned long long ull;

// Pre-transposed forward weights: slot0=W_in^T, slot1..4=Wl[i]^T, slot5=W_out^T
__device__ float g_wt[6 * HD * HD];
// sin(t*fw + fb) per layer
__device__ float g_cvec[4 * HD];
// layer-input checkpoints u_i, [4][NB][HD]
__device__ float g_u[(size_t)4 * NB * HD];

__global__ void prep_kernel(const float* __restrict__ t, const float* __restrict__ fw,
                            const float* __restrict__ fb, const float* __restrict__ W_in,
                            const float* __restrict__ Wl, const float* __restrict__ W_out) {
    int b = blockIdx.x;
    if (b < 6) {
        const float* src = (b == 0) ? W_in : (b <= 4 ? Wl + (b - 1) * HD * HD : W_out);
        float* dst = g_wt + b * HD * HD;
        for (int idx = threadIdx.x; idx < HD * HD; idx += blockDim.x) {
            int r = idx >> 7, c = idx & 127;
            dst[c * HD + r] = src[idx];
        }
    } else {
        float tv = t[0];
        for (int idx = threadIdx.x; idx < 4 * HD; idx += blockDim.x)
            g_cvec[idx] = sinf(tv * fw[idx] + fb[idx]);
    }
}

__device__ __forceinline__ ull ffma2(ull a, ull b, ull c) {
    ull d;
    asm("fma.rn.f32x2 %0, %1, %2, %3;" : "=l"(d) : "l"(a), "l"(b), "l"(c));
    return d;
}
__device__ __forceinline__ ull dup2(float x) {
    unsigned u = __float_as_uint(x);
    return ((ull)u << 32) | (ull)u;
}
__device__ __forceinline__ float plo(ull p) { return __uint_as_float((unsigned)p); }
__device__ __forceinline__ float phi(ull p) { return __uint_as_float((unsigned)(p >> 32)); }

__device__ __forceinline__ float wsum(float v) {
#pragma unroll
    for (int o = 16; o > 0; o >>= 1) v += __shfl_xor_sync(0xffffffffu, v, o);
    return v;
}

__device__ __forceinline__ float softplus_f(float x) {
    return fmaxf(x, 0.f) + __logf(1.f + __expf(-fabsf(x)));
}

__device__ __forceinline__ void stage16k(float* __restrict__ dst, const float* __restrict__ src,
                                         int tid) {
    const float4* s = reinterpret_cast<const float4*>(src);
    float4* d = reinterpret_cast<float4*>(dst);
#pragma unroll
    for (int i = 0; i < (HD * HD / 4) / THREADS; i++) d[tid + i * THREADS] = s[tid + i * THREADS];
}

// C[r][c] = sum_k A[r][k]*M[k][c]; warp owns 8 rows (r0..r0+7), lane owns 4 cols (c0..c0+3).
// A is stored in smem as duplicated f32 pairs (v,v) so one broadcast LDS.128 covers 2 k-steps.
__device__ __forceinline__ void gemm64(const ull* __restrict__ sA2, const float* __restrict__ sM,
                                       ull acc[8][2], int r0, int c0) {
#pragma unroll
    for (int rr = 0; rr < 8; rr++) { acc[rr][0] = 0ull; acc[rr][1] = 0ull; }
#pragma unroll 4
    for (int k = 0; k < HD; k += 2) {
        ulonglong2 m0 = *reinterpret_cast<const ulonglong2*>(&sM[k * HD + c0]);
        ulonglong2 m1 = *reinterpret_cast<const ulonglong2*>(&sM[(k + 1) * HD + c0]);
#pragma unroll
        for (int rr = 0; rr < 8; rr++) {
            ulonglong2 av = *reinterpret_cast<const ulonglong2*>(&sA2[(r0 + rr) * HD + k]);
            acc[rr][0] = ffma2(av.x, m0.x, acc[rr][0]);
            acc[rr][1] = ffma2(av.x, m0.y, acc[rr][1]);
            acc[rr][0] = ffma2(av.y, m1.x, acc[rr][0]);
            acc[rr][1] = ffma2(av.y, m1.y, acc[rr][1]);
        }
    }
}

__global__ __launch_bounds__(THREADS) void fused_kernel(
    const float* __restrict__ p, const float* __restrict__ w,
    const float* __restrict__ W_in, const float* __restrict__ b_in,
    const float* __restrict__ gamma, const float* __restrict__ beta,
    const float* __restrict__ Wl, const float* __restrict__ bl,
    const float* __restrict__ W_out, const float* __restrict__ b_out,
    float* __restrict__ dp, float* __restrict__ dw) {
    extern __shared__ float smem[];
    float* sM = smem;                                 // HD*HD floats (64KB)
    ull* sA2 = reinterpret_cast<ull*>(smem + HD * HD);  // TILE*HD pairs (64KB)
    float* sStats = reinterpret_cast<float*>(sA2 + TILE * HD);  // 4*TILE*2 floats

    const int tid = threadIdx.x;
    const int lane = tid & 31, warp = tid >> 5;
    const int r0 = warp * 8, c0 = lane * 4;
    const size_t rowBase = (size_t)blockIdx.x * TILE;

    ull acc[8][2];

    // ---------------- forward ----------------
    // load p tile -> sA2 (duplicated pairs)
#pragma unroll
    for (int rr = 0; rr < 8; rr++) {
        float4 v = *reinterpret_cast<const float4*>(&p[(rowBase + r0 + rr) * HD + c0]);
        ulonglong2 q0 = make_ulonglong2(dup2(v.x), dup2(v.y));
        ulonglong2 q1 = make_ulonglong2(dup2(v.z), dup2(v.w));
        *reinterpret_cast<ulonglong2*>(&sA2[(r0 + rr) * HD + c0]) = q0;
        *reinterpret_cast<ulonglong2*>(&sA2[(r0 + rr) * HD + c0 + 2]) = q1;
    }
    stage16k(sM, g_wt, tid);
    __syncthreads();
    gemm64(sA2, sM, acc, r0, c0);
    {
        float4 b = *reinterpret_cast<const float4*>(&b_in[c0]);
        ull b01 = ((ull)__float_as_uint(b.y) << 32) | __float_as_uint(b.x);
        ull b23 = ((ull)__float_as_uint(b.w) << 32) | __float_as_uint(b.z);
        ull one = dup2(1.f);
#pragma unroll
        for (int rr = 0; rr < 8; rr++) {
            acc[rr][0] = ffma2(one, b01, acc[rr][0]);
            acc[rr][1] = ffma2(one, b23, acc[rr][1]);
        }
    }

#pragma unroll 1
    for (int i = 0; i < 4; i++) {
        float4 cv = *reinterpret_cast<const float4*>(&g_cvec[i * HD + c0]);
        float4 gm = *reinterpret_cast<const float4*>(&gamma[i * HD + c0]);
        float4 bt = *reinterpret_cast<const float4*>(&beta[i * HD + c0]);
        float nv[8][4];
#pragma unroll
        for (int rr = 0; rr < 8; rr++) {
            float u0 = plo(acc[rr][0]), u1 = phi(acc[rr][0]);
            float u2 = plo(acc[rr][1]), u3 = phi(acc[rr][1]);
            // checkpoint u_i to global scratch
            *reinterpret_cast<float4*>(&g_u[((size_t)i * NB + rowBase + r0 + rr) * HD + c0]) =
                make_float4(u0, u1, u2, u3);
            float s0 = softplus_f(u0 + cv.x);
            float s1 = softplus_f(u1 + cv.y);
            float s2 = softplus_f(u2 + cv.z);
            float s3 = softplus_f(u3 + cv.w);
            float mu = wsum(s0 + s1 + s2 + s3) * (1.f / HD);
            float d0 = s0 - mu, d1 = s1 - mu, d2 = s2 - mu, d3 = s3 - mu;
            float var = wsum(d0 * d0 + d1 * d1 + d2 * d2 + d3 * d3) * (1.f / HD);
            float inv = rsqrtf(var + 1e-5f);
            if (lane == 0) {
                sStats[(i * TILE + r0 + rr) * 2] = mu;
                sStats[(i * TILE + r0 + rr) * 2 + 1] = inv;
            }
            nv[rr][0] = d0 * inv * gm.x + bt.x;
            nv[rr][1] = d1 * inv * gm.y + bt.y;
            nv[rr][2] = d2 * inv * gm.z + bt.z;
            nv[rr][3] = d3 * inv * gm.w + bt.w;
        }
        __syncthreads();
#pragma unroll
        for (int rr = 0; rr < 8; rr++) {
            *reinterpret_cast<ulonglong2*>(&sA2[(r0 + rr) * HD + c0]) =
                make_ulonglong2(dup2(nv[rr][0]), dup2(nv[rr][1]));
            *reinterpret_cast<ulonglong2*>(&sA2[(r0 + rr) * HD + c0 + 2]) =
                make_ulonglong2(dup2(nv[rr][2]), dup2(nv[rr][3]));
        }
        stage16k(sM, g_wt + (1 + i) * HD * HD, tid);
        __syncthreads();
        gemm64(sA2, sM, acc, r0, c0);
        float4 b = *reinterpret_cast<const float4*>(&bl[i * HD + c0]);
        ull one = dup2(1.f);
        ull b01 = ((ull)__float_as_uint(b.y) << 32) | __float_as_uint(b.x);
        ull b23 = ((ull)__float_as_uint(b.w) << 32) | __float_as_uint(b.z);
#pragma unroll
        for (int rr = 0; rr < 8; rr++) {
            acc[rr][0] = ffma2(one, b01, acc[rr][0]);
            acc[rr][1] = ffma2(one, b23, acc[rr][1]);
        }
    }

    // output projection -> dp
    __syncthreads();
#pragma unroll
    for (int rr = 0; rr < 8; rr++) {
        *reinterpret_cast<ulonglong2*>(&sA2[(r0 + rr) * HD + c0]) =
            make_ulonglong2(dup2(plo(acc[rr][0])), dup2(phi(acc[rr][0])));
        *reinterpret_cast<ulonglong2*>(&sA2[(r0 + rr) * HD + c0 + 2]) =
            make_ulonglong2(dup2(plo(acc[rr][1])), dup2(phi(acc[rr][1])));
    }
    stage16k(sM, g_wt + 5 * HD * HD, tid);
    __syncthreads();
    gemm64(sA2, sM, acc, r0, c0);
    {
        float4 b = *reinterpret_cast<const float4*>(&b_out[c0]);
#pragma unroll
        for (int rr = 0; rr < 8; rr++) {
            float4 v = make_float4(plo(acc[rr][0]) + b.x, phi(acc[rr][0]) + b.y,
                                   plo(acc[rr][1]) + b.z, phi(acc[rr][1]) + b.w);
            *reinterpret_cast<float4*>(&dp[(rowBase + r0 + rr) * HD + c0]) = v;
        }
    }

    // ---------------- backward ----------------
    __syncthreads();
#pragma unroll
    for (int rr = 0; rr < 8; rr++) {
        float4 v = *reinterpret_cast<const float4*>(&w[(rowBase + r0 + rr) * HD + c0]);
        *reinterpret_cast<ulonglong2*>(&sA2[(r0 + rr) * HD + c0]) =
            make_ulonglong2(dup2(v.x), dup2(v.y));
        *reinterpret_cast<ulonglong2*>(&sA2[(r0 + rr) * HD + c0 + 2]) =
            make_ulonglong2(dup2(v.z), dup2(v.w));
    }
    stage16k(sM, W_out, tid);  // raw row-major: g = W_out^T w
    __syncthreads();
    gemm64(sA2, sM, acc, r0, c0);

#pragma unroll 1
    for (int i = 3; i >= 0; i--) {
        // prefetch u_i before the GEMM that hides its latency
        float4 uf[8];
#pragma unroll
        for (int rr = 0; rr < 8; rr++)
            uf[rr] = *reinterpret_cast<const float4*>(
                &g_u[((size_t)i * NB + rowBase + r0 + rr) * HD + c0]);
        __syncthreads();
#pragma unroll
        for (int rr = 0; rr < 8; rr++) {
            *reinterpret_cast<ulonglong2*>(&sA2[(r0 + rr) * HD + c0]) =
                make_ulonglong2(dup2(plo(acc[rr][0])), dup2(phi(acc[rr][0])));
            *reinterpret_cast<ulonglong2*>(&sA2[(r0 + rr) * HD + c0 + 2]) =
                make_ulonglong2(dup2(plo(acc[rr][1])), dup2(phi(acc[rr][1])));
        }
        stage16k(sM, Wl + i * HD * HD, tid);  // raw: gx = Wl_i^T g
        __syncthreads();
        gemm64(sA2, sM, acc, r0, c0);
        float4 cv = *reinterpret_cast<const float4*>(&g_cvec[i * HD + c0]);
        float4 gm = *reinterpret_cast<const float4*>(&gamma[i * HD + c0]);
#pragma unroll
        for (int rr = 0; rr < 8; rr++) {
            float mu = sStats[(i * TILE + r0 + rr) * 2];
            float inv = sStats[(i * TILE + r0 + rr) * 2 + 1];
            float a0 = uf[rr].x + cv.x, a1 = uf[rr].y + cv.y;
            float a2 = uf[rr].z + cv.z, a3 = uf[rr].w + cv.w;
            float e0 = __expf(-fabsf(a0)), e1 = __expf(-fabsf(a1));
            float e2 = __expf(-fabsf(a2)), e3 = __expf(-fabsf(a3));
            float r0i = __fdividef(1.f, 1.f + e0), r1i = __fdividef(1.f, 1.f + e1);
            float r2i = __fdividef(1.f, 1.f + e2), r3i = __fdividef(1.f, 1.f + e3);
            float sg0 = (a0 >= 0.f ? 1.f : e0) * r0i, sg1 = (a1 >= 0.f ? 1.f : e1) * r1i;
            float sg2 = (a2 >= 0.f ? 1.f : e2) * r2i, sg3 = (a3 >= 0.f ? 1.f : e3) * r3i;
            float xh0 = (fmaxf(a0, 0.f) + __logf(1.f + e0) - mu) * inv;
            float xh1 = (fmaxf(a1, 0.f) + __logf(1.f + e1) - mu) * inv;
            float xh2 = (fmaxf(a2, 0.f) + __logf(1.f + e2) - mu) * inv;
            float xh3 = (fmaxf(a3, 0.f) + __logf(1.f + e3) - mu) * inv;
            float gx0 = plo(acc[rr][0]) * gm.x, gx1 = phi(acc[rr][0]) * gm.y;
            float gx2 = plo(acc[rr][1]) * gm.z, gx3 = phi(acc[rr][1]) * gm.w;
            float m1 = wsum(gx0 + gx1 + gx2 + gx3) * (1.f / HD);
            float m2 = wsum(gx0 * xh0 + gx1 * xh1 + gx2 * xh2 + gx3 * xh3) * (1.f / HD);
            float o0 = inv * (gx0 - m1 - xh0 * m2) * sg0;
            float o1 = inv * (gx1 - m1 - xh1 * m2) * sg1;
            float o2 = inv * (gx2 - m1 - xh2 * m2) * sg2;
            float o3 = inv * (gx3 - m1 - xh3 * m2) * sg3;
            acc[rr][0] = ((ull)__float_as_uint(o1) << 32) | __float_as_uint(o0);
            acc[rr][1] = ((ull)__float_as_uint(o3) << 32) | __float_as_uint(o2);
        }
    }

    __syncthreads();
#pragma unroll
    for (int rr = 0; rr < 8; rr++) {
        *reinterpret_cast<ulonglong2*>(&sA2[(r0 + rr) * HD + c0]) =
            make_ulonglong2(dup2(plo(acc[rr][0])), dup2(phi(acc[rr][0])));
        *reinterpret_cast<ulonglong2*>(&sA2[(r0 + rr) * HD + c0 + 2]) =
            make_ulonglong2(dup2(plo(acc[rr][1])), dup2(phi(acc[rr][1])));
    }
    stage16k(sM, W_in, tid);  // raw: gp = W_in^T g
    __syncthreads();
    gemm64(sA2, sM, acc, r0, c0);
#pragma unroll
    for (int rr = 0; rr < 8; rr++)
        *reinterpret_cast<float4*>(&dw[(rowBase + r0 + rr) * HD + c0]) =
            make_float4(-plo(acc[rr][0]), -phi(acc[rr][0]), -plo(acc[rr][1]), -phi(acc[rr][1]));
}

extern "C" void kernel_launch(void* const* d_in, const int* in_sizes, int n_in,
                              void* d_out, int out_size) {
    const float* t     = (const float*)d_in[0];
    const float* p     = (const float*)d_in[1];
    const float* w     = (const float*)d_in[2];
    const float* W_in  = (const float*)d_in[3];
    const float* b_in  = (const float*)d_in[4];
    const float* fw    = (const float*)d_in[5];
    const float* fb    = (const float*)d_in[6];
    const float* gamma = (const float*)d_in[7];
    const float* beta  = (const float*)d_in[8];
    const float* Wl    = (const float*)d_in[9];
    const float* bl    = (const float*)d_in[10];
    const float* W_out = (const float*)d_in[11];
    const float* b_out = (const float*)d_in[12];

    int nrows = in_sizes[1] / HD;  // B
    float* dp = (float*)d_out;
    float* dw = dp + (size_t)nrows * HD;

    size_t smem = (size_t)(HD * HD) * sizeof(float) + (size_t)(TILE * HD) * sizeof(ull) +
                  (size_t)(4 * TILE * 2) * sizeof(float);
    cudaFuncSetAttribute(fused_kernel, cudaFuncAttributeMaxDynamicSharedMemorySize, (int)smem);

    prep_kernel<<<7, 256>>>(t, fw, fb, W_in, Wl, W_out);
    fused_kernel<<<nrows / TILE, THREADS, smem>>>(p, w, W_in, b_in, gamma, beta, Wl, bl,
                                                  W_out, b_out, dp, dw);
}

// round 4
// speedup vs baseline: 2.1478x; 1.1240x over previous
#include <cuda_runtime.h>
#include <math.h>

#define HD 128
#define HALFK 64
#define TILE 64
#define THREADS 256
#define NBMAX 131072

typedef unsigned long long ull;

// Pair-layout weights: slot s, entry [k2*HD + c] = pack(W'[c][2*k2], W'[c][2*k2+1])
// slots 0..5  forward  (W' = W, row-major [out][in]):   0=W_in, 1..4=Wl, 5=W_out
// slots 6..11 backward (W' = W^T):                      6=W_in, 7..10=Wl, 11=W_out
__device__ ull g_wt[12 * HALFK * HD];
__device__ float g_cvec[4 * HD];
// layer-input checkpoints, lane-permuted chunks: [(i*NB+row)*HD + 4*lane + j] = u[col=lane+32j]
__device__ float g_u[(size_t)4 * NBMAX * HD];

__global__ void prep_kernel(const float* __restrict__ t, const float* __restrict__ fw,
                            const float* __restrict__ fb, const float* __restrict__ W_in,
                            const float* __restrict__ Wl, const float* __restrict__ W_out) {
    int b = blockIdx.x;
    if (b < 12) {
        int m = b % 6;
        const float* src = (m == 0) ? W_in : (m <= 4 ? Wl + (m - 1) * HD * HD : W_out);
        bool fwd = (b < 6);
        ull* dst = g_wt + (size_t)b * HALFK * HD;
        for (int idx = threadIdx.x; idx < HALFK * HD; idx += blockDim.x) {
            int k2 = idx >> 7, c = idx & 127;
            float lo, hi;
            if (fwd) { lo = src[c * HD + 2 * k2];     hi = src[c * HD + 2 * k2 + 1]; }
            else     { lo = src[(2 * k2) * HD + c];   hi = src[(2 * k2 + 1) * HD + c]; }
            dst[idx] = ((ull)__float_as_uint(hi) << 32) | (ull)__float_as_uint(lo);
        }
    } else {
        float tv = t[0];
        for (int idx = threadIdx.x; idx < 4 * HD; idx += blockDim.x)
            g_cvec[idx] = sinf(tv * fw[idx] + fb[idx]);
    }
}

__device__ __forceinline__ ull ffma2(ull a, ull b, ull c) {
    ull d;
    asm("fma.rn.f32x2 %0, %1, %2, %3;" : "=l"(d) : "l"(a), "l"(b), "l"(c));
    return d;
}
__device__ __forceinline__ float plo(ull p) { return __uint_as_float((unsigned)p); }
__device__ __forceinline__ float phi(ull p) { return __uint_as_float((unsigned)(p >> 32)); }
__device__ __forceinline__ float pcomb(ull p) { return plo(p) + phi(p); }

__device__ __forceinline__ float wsum(float v) {
#pragma unroll
    for (int o = 16; o > 0; o >>= 1) v += __shfl_xor_sync(0xffffffffu, v, o);
    return v;
}

__device__ __forceinline__ float softplus_f(float x) {
    return fmaxf(x, 0.f) + __logf(1.f + __expf(-fabsf(x)));
}

// copy one 64KB pair-layout weight matrix into smem
__device__ __forceinline__ void stageW(ull* __restrict__ dst, const ull* __restrict__ src,
                                       int tid) {
    const float4* s = reinterpret_cast<const float4*>(src);
    float4* d = reinterpret_cast<float4*>(dst);
#pragma unroll
    for (int i = 0; i < 16; i++) d[tid + i * THREADS] = s[tid + i * THREADS];
}

// C[r][c] = sum_k A[r][k]*M'[c][k]; warp owns rows r0..r0+7; lane owns cols lane+32j.
// acc[rr][j] is an f32 pair holding (even-k partial, odd-k partial).
__device__ __forceinline__ void gemmP(const float* __restrict__ sA, const ull* __restrict__ sMp,
                                      ull acc[8][4], int r0, int lane) {
#pragma unroll
    for (int rr = 0; rr < 8; rr++)
#pragma unroll
        for (int j = 0; j < 4; j++) acc[rr][j] = 0ull;
#pragma unroll 2
    for (int i = 0; i < 32; i++) {  // 4 k-values per iteration
        ull m0[4], m1[4];
#pragma unroll
        for (int j = 0; j < 4; j++) {
            m0[j] = sMp[(2 * i) * HD + lane + 32 * j];
            m1[j] = sMp[(2 * i + 1) * HD + lane + 32 * j];
        }
#pragma unroll
        for (int rr = 0; rr < 8; rr++) {
            ulonglong2 av = *reinterpret_cast<const ulonglong2*>(&sA[(r0 + rr) * HD + 4 * i]);
#pragma unroll
            for (int j = 0; j < 4; j++) {
                acc[rr][j] = ffma2(av.x, m0[j], acc[rr][j]);
                acc[rr][j] = ffma2(av.y, m1[j], acc[rr][j]);
            }
        }
    }
}

__global__ __launch_bounds__(THREADS, 2) void fused_kernel(
    const float* __restrict__ p, const float* __restrict__ w,
    const float* __restrict__ b_in, const float* __restrict__ gamma,
    const float* __restrict__ bl, const float* __restrict__ beta,
    const float* __restrict__ b_out, float* __restrict__ dp, float* __restrict__ dw,
    int NB) {
    extern __shared__ char smemraw[];
    ull* sMp = reinterpret_cast<ull*>(smemraw);                       // 64KB
    float* sA = reinterpret_cast<float*>(smemraw + 65536);            // 32KB
    float* sStats = reinterpret_cast<float*>(smemraw + 65536 + 32768);// 2KB

    const int tid = threadIdx.x;
    const int lane = tid & 31, warp = tid >> 5;
    const int r0 = warp * 8;
    const size_t rowBase = (size_t)blockIdx.x * TILE;

    ull acc[8][4];
    float uv[8][4];

    // ---------------- forward ----------------
    {
        const float4* s = reinterpret_cast<const float4*>(p + rowBase * HD);
        float4* d = reinterpret_cast<float4*>(sA);
#pragma unroll
        for (int i = 0; i < 8; i++) d[tid + i * THREADS] = s[tid + i * THREADS];
    }
    stageW(sMp, g_wt, tid);
    __syncthreads();
    gemmP(sA, sMp, acc, r0, lane);
    {
        float cb[4];
#pragma unroll
        for (int j = 0; j < 4; j++) cb[j] = b_in[lane + 32 * j];
#pragma unroll
        for (int rr = 0; rr < 8; rr++)
#pragma unroll
            for (int j = 0; j < 4; j++) uv[rr][j] = pcomb(acc[rr][j]) + cb[j];
    }

#pragma unroll 1
    for (int i = 0; i < 4; i++) {
        float cv[4], gm[4], bt[4];
#pragma unroll
        for (int j = 0; j < 4; j++) {
            cv[j] = g_cvec[i * HD + lane + 32 * j];
            gm[j] = gamma[i * HD + lane + 32 * j];
            bt[j] = beta[i * HD + lane + 32 * j];
        }
        float nv[8][4];
#pragma unroll
        for (int rr = 0; rr < 8; rr++) {
            *reinterpret_cast<float4*>(&g_u[((size_t)i * NB + rowBase + r0 + rr) * HD + 4 * lane]) =
                make_float4(uv[rr][0], uv[rr][1], uv[rr][2], uv[rr][3]);
            float s0 = softplus_f(uv[rr][0] + cv[0]);
            float s1 = softplus_f(uv[rr][1] + cv[1]);
            float s2 = softplus_f(uv[rr][2] + cv[2]);
            float s3 = softplus_f(uv[rr][3] + cv[3]);
            float mu = wsum(s0 + s1 + s2 + s3) * (1.f / HD);
            float d0 = s0 - mu, d1 = s1 - mu, d2 = s2 - mu, d3 = s3 - mu;
            float var = wsum(d0 * d0 + d1 * d1 + d2 * d2 + d3 * d3) * (1.f / HD);
            float inv = rsqrtf(var + 1e-5f);
            if (lane == 0) {
                sStats[(i * TILE + r0 + rr) * 2] = mu;
                sStats[(i * TILE + r0 + rr) * 2 + 1] = inv;
            }
            nv[rr][0] = d0 * inv * gm[0] + bt[0];
            nv[rr][1] = d1 * inv * gm[1] + bt[1];
            nv[rr][2] = d2 * inv * gm[2] + bt[2];
            nv[rr][3] = d3 * inv * gm[3] + bt[3];
        }
        __syncthreads();
#pragma unroll
        for (int rr = 0; rr < 8; rr++)
#pragma unroll
            for (int j = 0; j < 4; j++) sA[(r0 + rr) * HD + lane + 32 * j] = nv[rr][j];
        stageW(sMp, g_wt + (size_t)(1 + i) * HALFK * HD, tid);
        __syncthreads();
        gemmP(sA, sMp, acc, r0, lane);
        float cb[4];
#pragma unroll
        for (int j = 0; j < 4; j++) cb[j] = bl[i * HD + lane + 32 * j];
#pragma unroll
        for (int rr = 0; rr < 8; rr++)
#pragma unroll
            for (int j = 0; j < 4; j++) uv[rr][j] = pcomb(acc[rr][j]) + cb[j];
    }

    // output projection -> dp
    __syncthreads();
#pragma unroll
    for (int rr = 0; rr < 8; rr++)
#pragma unroll
        for (int j = 0; j < 4; j++) sA[(r0 + rr) * HD + lane + 32 * j] = uv[rr][j];
    stageW(sMp, g_wt + (size_t)5 * HALFK * HD, tid);
    __syncthreads();
    gemmP(sA, sMp, acc, r0, lane);
    {
        float cb[4];
#pragma unroll
        for (int j = 0; j < 4; j++) cb[j] = b_out[lane + 32 * j];
#pragma unroll
        for (int rr = 0; rr < 8; rr++)
#pragma unroll
            for (int j = 0; j < 4; j++)
                dp[(rowBase + r0 + rr) * HD + lane + 32 * j] = pcomb(acc[rr][j]) + cb[j];
    }

    // ---------------- backward ----------------
    __syncthreads();
    {
        const float4* s = reinterpret_cast<const float4*>(w + rowBase * HD);
        float4* d = reinterpret_cast<float4*>(sA);
#pragma unroll
        for (int i = 0; i < 8; i++) d[tid + i * THREADS] = s[tid + i * THREADS];
    }
    stageW(sMp, g_wt + (size_t)11 * HALFK * HD, tid);  // W_out^T
    __syncthreads();
    gemmP(sA, sMp, acc, r0, lane);  // g = W_out^T w
    float gv[8][4];
#pragma unroll
    for (int rr = 0; rr < 8; rr++)
#pragma unroll
        for (int j = 0; j < 4; j++) gv[rr][j] = pcomb(acc[rr][j]);

#pragma unroll 1
    for (int i = 3; i >= 0; i--) {
        float4 uf[8];
#pragma unroll
        for (int rr = 0; rr < 8; rr++)
            uf[rr] = *reinterpret_cast<const float4*>(
                &g_u[((size_t)i * NB + rowBase + r0 + rr) * HD + 4 * lane]);
        __syncthreads();
#pragma unroll
        for (int rr = 0; rr < 8; rr++)
#pragma unroll
            for (int j = 0; j < 4; j++) sA[(r0 + rr) * HD + lane + 32 * j] = gv[rr][j];
        stageW(sMp, g_wt + (size_t)(7 + i) * HALFK * HD, tid);  // Wl_i^T
        __syncthreads();
        gemmP(sA, sMp, acc, r0, lane);  // gx_pre = Wl_i^T g
        float cv[4], gm[4];
#pragma unroll
        for (int j = 0; j < 4; j++) {
            cv[j] = g_cvec[i * HD + lane + 32 * j];
            gm[j] = gamma[i * HD + lane + 32 * j];
        }
#pragma unroll
        for (int rr = 0; rr < 8; rr++) {
            float mu = sStats[(i * TILE + r0 + rr) * 2];
            float inv = sStats[(i * TILE + r0 + rr) * 2 + 1];
            float a0 = uf[rr].x + cv[0], a1 = uf[rr].y + cv[1];
            float a2 = uf[rr].z + cv[2], a3 = uf[rr].w + cv[3];
            float e0 = __expf(-fabsf(a0)), e1 = __expf(-fabsf(a1));
            float e2 = __expf(-fabsf(a2)), e3 = __expf(-fabsf(a3));
            float r0i = __fdividef(1.f, 1.f + e0), r1i = __fdividef(1.f, 1.f + e1);
            float r2i = __fdividef(1.f, 1.f + e2), r3i = __fdividef(1.f, 1.f + e3);
            float sg0 = (a0 >= 0.f ? 1.f : e0) * r0i, sg1 = (a1 >= 0.f ? 1.f : e1) * r1i;
            float sg2 = (a2 >= 0.f ? 1.f : e2) * r2i, sg3 = (a3 >= 0.f ? 1.f : e3) * r3i;
            float xh0 = (fmaxf(a0, 0.f) + __logf(1.f + e0) - mu) * inv;
            float xh1 = (fmaxf(a1, 0.f) + __logf(1.f + e1) - mu) * inv;
            float xh2 = (fmaxf(a2, 0.f) + __logf(1.f + e2) - mu) * inv;
            float xh3 = (fmaxf(a3, 0.f) + __logf(1.f + e3) - mu) * inv;
            float gx0 = pcomb(acc[rr][0]) * gm[0], gx1 = pcomb(acc[rr][1]) * gm[1];
            float gx2 = pcomb(acc[rr][2]) * gm[2], gx3 = pcomb(acc[rr][3]) * gm[3];
            float m1 = wsum(gx0 + gx1 + gx2 + gx3) * (1.f / HD);
            float m2 = wsum(gx0 * xh0 + gx1 * xh1 + gx2 * xh2 + gx3 * xh3) * (1.f / HD);
            gv[rr][0] = inv * (gx0 - m1 - xh0 * m2) * sg0;
            gv[rr][1] = inv * (gx1 - m1 - xh1 * m2) * sg1;
            gv[rr][2] = inv * (gx2 - m1 - xh2 * m2) * sg2;
            gv[rr][3] = inv * (gx3 - m1 - xh3 * m2) * sg3;
        }
    }

    __syncthreads();
#pragma unroll
    for (int rr = 0; rr < 8; rr++)
#pragma unroll
        for (int j = 0; j < 4; j++) sA[(r0 + rr) * HD + lane + 32 * j] = gv[rr][j];
    stageW(sMp, g_wt + (size_t)6 * HALFK * HD, tid);  // W_in^T
    __syncthreads();
    gemmP(sA, sMp, acc, r0, lane);  // gp = W_in^T g
#pragma unroll
    for (int rr = 0; rr < 8; rr++)
#pragma unroll
        for (int j = 0; j < 4; j++)
            dw[(rowBase + r0 + rr) * HD + lane + 32 * j] = -pcomb(acc[rr][j]);
}

extern "C" void kernel_launch(void* const* d_in, const int* in_sizes, int n_in,
                              void* d_out, int out_size) {
    const float* t     = (const float*)d_in[0];
    const float* p     = (const float*)d_in[1];
    const float* w     = (const float*)d_in[2];
    const float* W_in  = (const float*)d_in[3];
    const float* b_in  = (const float*)d_in[4];
    const float* fw    = (const float*)d_in[5];
    const float* fb    = (const float*)d_in[6];
    const float* gamma = (const float*)d_in[7];
    const float* beta  = (const float*)d_in[8];
    const float* Wl    = (const float*)d_in[9];
    const float* bl    = (const float*)d_in[10];
    const float* W_out = (const float*)d_in[11];
    const float* b_out = (const float*)d_in[12];

    int nrows = in_sizes[1] / HD;  // B
    float* dp = (float*)d_out;
    float* dw = dp + (size_t)nrows * HD;

    size_t smem = 65536 + 32768 + 4 * TILE * 2 * sizeof(float);  // 100352 B
    cudaFuncSetAttribute(fused_kernel, cudaFuncAttributeMaxDynamicSharedMemorySize, (int)smem);

    prep_kernel<<<13, 256>>>(t, fw, fb, W_in, Wl, W_out);
    fused_kernel<<<nrows / TILE, THREADS, smem>>>(p, w, b_in, gamma, bl, beta, b_out,
                                                  dp, dw, nrows);
}

// round 8
// speedup vs baseline: 5.6084x; 2.6113x over previous
#include <cuda_runtime.h>
#include <cuda_bf16.h>
#include <math.h>
#include <stdint.h>

#define HD 128
#define MTILE 128
#define THREADS 256
#define WSTRIDE 136            // padded k-stride in bf16 elems (conflict-free ldmatrix)
#define SLOT_BYTES 69632       // (hi+lo) * 128 rows * 136 * 2B
#define LO_BYTES 34816         // byte offset of lo image within a slot

// Weight images: slots 0..5 forward (B[n][k]=W[n][k]), 6..11 backward (B[n][k]=W[k][n])
__device__ __align__(16) unsigned char g_wimg[12 * SLOT_BYTES];
__device__ float g_fb[4 * HD];    // forward bias + sin(t*fw+fb), per layer
__device__ float2 g_gb[4 * HD];   // (gamma, beta)
// softplus checkpoints: [((i*nblk+blk)*16 + jj)*256 + tid] float4
__device__ float g_s[(size_t)4 * 1024 * 16 * 1024];

__global__ void prep_kernel(const float* __restrict__ t, const float* __restrict__ fw,
                            const float* __restrict__ fb, const float* __restrict__ W_in,
                            const float* __restrict__ Wl, const float* __restrict__ W_out,
                            const float* __restrict__ b_in, const float* __restrict__ bl,
                            const float* __restrict__ gamma, const float* __restrict__ beta) {
    int b = blockIdx.x;
    if (b < 12) {
        int m = b % 6;
        bool fwd = b < 6;
        const float* src = (m == 0) ? W_in : (m <= 4 ? Wl + (m - 1) * HD * HD : W_out);
        __nv_bfloat16* img = reinterpret_cast<__nv_bfloat16*>(g_wimg + (size_t)b * SLOT_BYTES);
        for (int idx = threadIdx.x; idx < HD * HD; idx += blockDim.x) {
            int n = idx >> 7, k = idx & 127;
            float v = fwd ? src[n * HD + k] : src[k * HD + n];
            __nv_bfloat16 h = __float2bfloat16(v);
            float r = v - __bfloat162float(h);
            img[n * WSTRIDE + k] = h;
            img[17408 + n * WSTRIDE + k] = __float2bfloat16(r);
        }
    } else {
        float tv = t[0];
        for (int c = threadIdx.x; c < 4 * HD; c += blockDim.x) {
            int i = c >> 7, cc = c & 127;
            float cv = sinf(tv * fw[c] + fb[c]);
            float bias = (i == 0) ? b_in[cc] : bl[(i - 1) * HD + cc];
            g_fb[c] = bias + cv;
            g_gb[c] = make_float2(gamma[c], beta[c]);
        }
    }
}

__device__ __forceinline__ uint32_t s2u(const void* p) {
    uint32_t a;
    asm("{ .reg .u64 t; cvta.to.shared.u64 t, %1; cvt.u32.u64 %0, t; }" : "=r"(a) : "l"(p));
    return a;
}
__device__ __forceinline__ unsigned packbf(float lo, float hi) {
    unsigned r;
    asm("cvt.rn.bf16x2.f32 %0, %1, %2;" : "=r"(r) : "f"(hi), "f"(lo));
    return r;
}
__device__ __forceinline__ void mma16816(float c[4], unsigned a0, unsigned a1, unsigned a2,
                                         unsigned a3, unsigned b0, unsigned b1) {
    asm volatile(
        "mma.sync.aligned.m16n8k16.row.col.f32.bf16.bf16.f32 "
        "{%0,%1,%2,%3},{%4,%5,%6,%7},{%8,%9},{%0,%1,%2,%3};"
        : "+f"(c[0]), "+f"(c[1]), "+f"(c[2]), "+f"(c[3])
        : "r"(a0), "r"(a1), "r"(a2), "r"(a3), "r"(b0), "r"(b1));
}
#define CP_COMMIT() asm volatile("cp.async.commit_group;" ::: "memory")
#define CP_WAIT1() asm volatile("cp.async.wait_group 1;" ::: "memory")
#define CP_WAIT0() asm volatile("cp.async.wait_group 0;" ::: "memory")

__device__ __forceinline__ void stageAsync(char* dst, int slot, int tid) {
    const char* src = (const char*)g_wimg + (size_t)slot * SLOT_BYTES;
    uint32_t d = s2u(dst);
#pragma unroll
    for (int i = 0; i < 17; i++) {
        int off = (tid + i * THREADS) * 16;
        asm volatile("cp.async.cg.shared.global [%0], [%1], 16;" ::"r"(d + off), "l"(src + off)
                     : "memory");
    }
}

__device__ __forceinline__ float softplus_f(float x) {
    return fmaxf(x, 0.f) + __logf(1.f + __expf(-fabsf(x)));
}
__device__ __forceinline__ float qred(float v) {  // sum over 4-lane quad
    v += __shfl_xor_sync(0xffffffffu, v, 1);
    v += __shfl_xor_sync(0xffffffffu, v, 2);
    return v;
}

// GEMM: C[128x128] += act * B^T with bf16 hi/lo 3-product split.
__device__ __forceinline__ void gemmStep(uint32_t bbase, const float act[16][4], float C[16][4]) {
#pragma unroll
    for (int t = 0; t < 16; t++)
#pragma unroll
        for (int q = 0; q < 4; q++) C[t][q] = 0.f;
#pragma unroll
    for (int kt = 0; kt < 8; kt++) {
        unsigned ah[4], al[4];
#pragma unroll
        for (int j = 0; j < 2; j++) {
            int tt = 2 * kt + j;
            unsigned h0 = packbf(act[tt][0], act[tt][1]);
            unsigned h1 = packbf(act[tt][2], act[tt][3]);
            float l00 = act[tt][0] - __uint_as_float(h0 << 16);
            float l01 = act[tt][1] - __uint_as_float(h0 & 0xFFFF0000u);
            float l10 = act[tt][2] - __uint_as_float(h1 << 16);
            float l11 = act[tt][3] - __uint_as_float(h1 & 0xFFFF0000u);
            ah[2 * j] = h0;
            ah[2 * j + 1] = h1;
            al[2 * j] = packbf(l00, l01);
            al[2 * j + 1] = packbf(l10, l11);
        }
        uint32_t addr = bbase + kt * 32;
#pragma unroll
        for (int nt = 0; nt < 16; nt++) {
            unsigned bh0, bh1, bl0, bl1;
            asm volatile("ldmatrix.sync.aligned.m8n8.x4.shared.b16 {%0,%1,%2,%3}, [%4];"
                         : "=r"(bh0), "=r"(bh1), "=r"(bl0), "=r"(bl1)
                         : "r"(addr + nt * 2176));
            mma16816(C[nt], ah[0], ah[1], ah[2], ah[3], bh0, bh1);
            mma16816(C[nt], ah[0], ah[1], ah[2], ah[3], bl0, bl1);
            mma16816(C[nt], al[0], al[1], al[2], al[3], bh0, bh1);
        }
    }
}

__global__ __launch_bounds__(THREADS, 1) void fused_kernel(
    const float* __restrict__ p, const float* __restrict__ w, const float* __restrict__ bl,
    const float* __restrict__ b_out, float* __restrict__ dp, float* __restrict__ dw, int nblk) {
    extern __shared__ __align__(16) char sm[];
    const int tid = threadIdx.x, warp = tid >> 5, lane = tid & 31;
    const int gq = lane >> 3, lr = lane & 7, li = lane & 3, lg = lane >> 2;
    const int r0 = blockIdx.x * MTILE + warp * 16 + lg;  // thread's rows: r0 and r0+8
    const uint32_t smb = s2u(sm);
    const uint32_t laneByte = (uint32_t)(lr * 272 + (gq & 1) * 16 + (gq >> 1) * LO_BYTES);

    float C[16][4], act[16][4];
    float mus[4][2], invs[4][2];

    stageAsync(sm, 0, tid);
    CP_COMMIT();
    stageAsync(sm + SLOT_BYTES, 1, tid);
    CP_COMMIT();

    // load p tile into fragment layout
#pragma unroll
    for (int t = 0; t < 16; t++) {
        float2 v0 = *reinterpret_cast<const float2*>(&p[(size_t)r0 * HD + 8 * t + 2 * li]);
        float2 v1 = *reinterpret_cast<const float2*>(&p[(size_t)(r0 + 8) * HD + 8 * t + 2 * li]);
        act[t][0] = v0.x; act[t][1] = v0.y; act[t][2] = v1.x; act[t][3] = v1.y;
    }
    CP_WAIT1();
    __syncthreads();

#pragma unroll 1
    for (int g = 0; g < 12; g++) {
        gemmStep(smb + (unsigned)(g & 1) * SLOT_BYTES + laneByte, act, C);
        __syncthreads();
        bool issued = false;
        if (g + 2 < 12) {
            int gg = g + 2;
            stageAsync(sm + (size_t)(g & 1) * SLOT_BYTES, (gg < 6) ? gg : 17 - gg, tid);
            CP_COMMIT();
            issued = true;
        }

        if (g < 4) {  // forward LN layer g
            float p10 = 0.f, p20 = 0.f, p11 = 0.f, p21 = 0.f;
#pragma unroll
            for (int t = 0; t < 16; t++) {
                float2 fb2 = *reinterpret_cast<const float2*>(&g_fb[g * HD + 8 * t + 2 * li]);
                float s0 = softplus_f(C[t][0] + fb2.x);
                float s1 = softplus_f(C[t][1] + fb2.y);
                float s2 = softplus_f(C[t][2] + fb2.x);
                float s3 = softplus_f(C[t][3] + fb2.y);
                act[t][0] = s0; act[t][1] = s1; act[t][2] = s2; act[t][3] = s3;
                p10 += s0 + s1; p20 += s0 * s0 + s1 * s1;
                p11 += s2 + s3; p21 += s2 * s2 + s3 * s3;
            }
            {
                float4* dst = reinterpret_cast<float4*>(g_s) +
                              ((size_t)(g * nblk + blockIdx.x) * 16) * 256 + tid;
#pragma unroll
                for (int jj = 0; jj < 16; jj++)
                    dst[jj * 256] = make_float4(act[jj][0], act[jj][1], act[jj][2], act[jj][3]);
            }
            p10 = qred(p10); p20 = qred(p20); p11 = qred(p11); p21 = qred(p21);
            float mu0 = p10 * (1.f / HD), mu1 = p11 * (1.f / HD);
            float inv0 = rsqrtf(p20 * (1.f / HD) - mu0 * mu0 + 1e-5f);
            float inv1 = rsqrtf(p21 * (1.f / HD) - mu1 * mu1 + 1e-5f);
            mus[g][0] = mu0; mus[g][1] = mu1; invs[g][0] = inv0; invs[g][1] = inv1;
#pragma unroll
            for (int t = 0; t < 16; t++) {
                float4 gb = *reinterpret_cast<const float4*>(&g_gb[g * HD + 8 * t + 2 * li]);
                act[t][0] = (act[t][0] - mu0) * inv0 * gb.x + gb.y;
                act[t][1] = (act[t][1] - mu0) * inv0 * gb.z + gb.w;
                act[t][2] = (act[t][2] - mu1) * inv1 * gb.x + gb.y;
                act[t][3] = (act[t][3] - mu1) * inv1 * gb.z + gb.w;
            }
        } else if (g == 4) {
#pragma unroll
            for (int t = 0; t < 16; t++) {
                float2 b2 = *reinterpret_cast<const float2*>(&bl[3 * HD + 8 * t + 2 * li]);
                act[t][0] = C[t][0] + b2.x; act[t][1] = C[t][1] + b2.y;
                act[t][2] = C[t][2] + b2.x; act[t][3] = C[t][3] + b2.y;
            }
        } else if (g == 5) {
#pragma unroll
            for (int t = 0; t < 16; t++) {
                float2 b2 = *reinterpret_cast<const float2*>(&b_out[8 * t + 2 * li]);
                *reinterpret_cast<float2*>(&dp[(size_t)r0 * HD + 8 * t + 2 * li]) =
                    make_float2(C[t][0] + b2.x, C[t][1] + b2.y);
                *reinterpret_cast<float2*>(&dp[(size_t)(r0 + 8) * HD + 8 * t + 2 * li]) =
                    make_float2(C[t][2] + b2.x, C[t][3] + b2.y);
            }
#pragma unroll
            for (int t = 0; t < 16; t++) {
                float2 v0 = *reinterpret_cast<const float2*>(&w[(size_t)r0 * HD + 8 * t + 2 * li]);
                float2 v1 =
                    *reinterpret_cast<const float2*>(&w[(size_t)(r0 + 8) * HD + 8 * t + 2 * li]);
                act[t][0] = v0.x; act[t][1] = v0.y; act[t][2] = v1.x; act[t][3] = v1.y;
            }
        } else if (g == 6) {
#pragma unroll
            for (int t = 0; t < 16; t++)
#pragma unroll
                for (int q = 0; q < 4; q++) act[t][q] = C[t][q];
        } else if (g < 11) {  // backward LN layer i
            int i = 10 - g;
            float sarr[16][4];
            {
                const float4* src = reinterpret_cast<const float4*>(g_s) +
                                    ((size_t)(i * nblk + blockIdx.x) * 16) * 256 + tid;
#pragma unroll
                for (int jj = 0; jj < 16; jj++) {
                    float4 v = src[jj * 256];
                    sarr[jj][0] = v.x; sarr[jj][1] = v.y; sarr[jj][2] = v.z; sarr[jj][3] = v.w;
                }
            }
            float mu0 = mus[i][0], mu1 = mus[i][1], inv0 = invs[i][0], inv1 = invs[i][1];
            float p10 = 0.f, p20 = 0.f, p11 = 0.f, p21 = 0.f;
#pragma unroll
            for (int t = 0; t < 16; t++) {
                float4 gb = *reinterpret_cast<const float4*>(&g_gb[i * HD + 8 * t + 2 * li]);
                float gx0 = C[t][0] * gb.x, gx1 = C[t][1] * gb.z;
                float gx2 = C[t][2] * gb.x, gx3 = C[t][3] * gb.z;
                C[t][0] = gx0; C[t][1] = gx1; C[t][2] = gx2; C[t][3] = gx3;
                p10 += gx0 + gx1; p20 += gx0 * (sarr[t][0] - mu0) + gx1 * (sarr[t][1] - mu0);
                p11 += gx2 + gx3; p21 += gx2 * (sarr[t][2] - mu1) + gx3 * (sarr[t][3] - mu1);
            }
            p10 = qred(p10); p20 = qred(p20); p11 = qred(p11); p21 = qred(p21);
            float m10 = p10 * (1.f / HD), m20 = p20 * inv0 * (1.f / HD);
            float m11 = p11 * (1.f / HD), m21 = p21 * inv1 * (1.f / HD);
#pragma unroll
            for (int t = 0; t < 16; t++) {
                float s0 = sarr[t][0], s1 = sarr[t][1], s2 = sarr[t][2], s3 = sarr[t][3];
                act[t][0] = inv0 * (C[t][0] - m10 - (s0 - mu0) * inv0 * m20) * (1.f - __expf(-s0));
                act[t][1] = inv0 * (C[t][1] - m10 - (s1 - mu0) * inv0 * m20) * (1.f - __expf(-s1));
                act[t][2] = inv1 * (C[t][2] - m11 - (s2 - mu1) * inv1 * m21) * (1.f - __expf(-s2));
                act[t][3] = inv1 * (C[t][3] - m11 - (s3 - mu1) * inv1 * m21) * (1.f - __expf(-s3));
            }
        } else {  // g == 11: dw = -C
#pragma unroll
            for (int t = 0; t < 16; t++) {
                *reinterpret_cast<float2*>(&dw[(size_t)r0 * HD + 8 * t + 2 * li]) =
                    make_float2(-C[t][0], -C[t][1]);
                *reinterpret_cast<float2*>(&dw[(size_t)(r0 + 8) * HD + 8 * t + 2 * li]) =
                    make_float2(-C[t][2], -C[t][3]);
            }
        }

        if (g < 11) {
            if (issued) CP_WAIT1();
            else CP_WAIT0();
            __syncthreads();
        }
    }
}

extern "C" void kernel_launch(void* const* d_in, const int* in_sizes, int n_in,
                              void* d_out, int out_size) {
    const float* t     = (const float*)d_in[0];
    const float* p     = (const float*)d_in[1];
    const float* w     = (const float*)d_in[2];
    const float* W_in  = (const float*)d_in[3];
    const float* b_in  = (const float*)d_in[4];
    const float* fw    = (const float*)d_in[5];
    const float* fb    = (const float*)d_in[6];
    const float* gamma = (const float*)d_in[7];
    const float* beta  = (const float*)d_in[8];
    const float* Wl    = (const float*)d_in[9];
    const float* bl    = (const float*)d_in[10];
    const float* W_out = (const float*)d_in[11];
    const float* b_out = (const float*)d_in[12];

    int nrows = in_sizes[1] / HD;
    int nblk = nrows / MTILE;
    float* dp = (float*)d_out;
    float* dw = dp + (size_t)nrows * HD;

    size_t smem = 2 * SLOT_BYTES;
    cudaFuncSetAttribute(fused_kernel, cudaFuncAttributeMaxDynamicSharedMemorySize, (int)smem);

    prep_kernel<<<13, 256>>>(t, fw, fb, W_in, Wl, W_out, b_in, bl, gamma, beta);
    fused_kernel<<<nblk, THREADS, smem>>>(p, w, bl, b_out, dp, dw, nblk);
}